// round 2
// baseline (speedup 1.0000x reference)
#include <cuda_runtime.h>

// Problem constants (fixed by the reference)
#define BATCH    4
#define NPB      8192      // nodes per batch
#define KNBR     16        // neighbors
#define C        128       // channels in == channels out
#define ROWS     (BATCH * NPB)   // 32768 total rows

// Tiling
#define TM       64        // rows per tile
#define THREADS  256
#define HSTRIDE  132       // padded h-tile row stride (floats), 16B-aligned (132*4=528)
#define NTILES   (ROWS / TM)     // 512

// Shared memory layout (floats):
//   [0, 16384)                : sWt  (W transposed, [c][o])
//   [16384, 16384+TM*HSTRIDE) : sh_h (h tile, padded)  -- aliased by sWpad during init
//   then TM*KNBR ints         : sidx (neighbor float-offsets)
#define SMEM_FLOATS (C * C + TM * HSTRIDE)
#define SMEM_BYTES  (SMEM_FLOATS * 4 + TM * KNBR * 4)

__global__ __launch_bounds__(THREADS, 2)
void gin_fused_kernel(const float* __restrict__ x,
                      const void* __restrict__ ei_raw,
                      const float* __restrict__ W,
                      const float* __restrict__ bias,
                      const float* __restrict__ epsp,
                      float* __restrict__ out)
{
    extern __shared__ float smem[];
    float* sWt   = smem;                       // 128x128
    float* sbuf  = smem + C * C;
    float* sh_h  = sbuf;                       // TM x HSTRIDE
    int*   sidx  = (int*)(sbuf + TM * HSTRIDE);
    float* sWpad = sbuf;                       // alias: staging for W transpose

    const int tid = threadIdx.x;

    // ---------------- dtype sniff for edge_index (int32 vs int64) ----------------
    // If the buffer is int64 (values < 8192), every odd 32-bit word is 0.
    // If it is int32, those words are random indices in [0, 8192).
    // All sampled words lie within the first 524288 int32 words, which is
    // in-bounds for both layouts (edge_index[0] slice).
    const int* w32 = (const int*)ei_raw;
    int orv = 0;
    #pragma unroll
    for (int t = 0; t < 64; t++) orv |= w32[t * 8192 + 1];
    const bool is64 = (orv == 0);
    const long long* w64 = (const long long*)ei_raw;

    // ---------------- One-time: transpose W into sWt[c][o] ----------------
    #pragma unroll
    for (int half = 0; half < 2; half++) {
        for (int i = tid; i < 64 * 32; i += THREADS) {          // float4 units
            int o  = i >> 5;
            int c4 = i & 31;
            float4 v = *(const float4*)(W + (size_t)(half * 64 + o) * C + 4 * c4);
            *(float4*)(sWpad + o * HSTRIDE + 4 * c4) = v;
        }
        __syncthreads();
        for (int i = tid; i < 64 * C; i += THREADS) {
            int oo = i & 63;        // lanes consecutive in o -> conflict-free sWt store
            int c  = i >> 6;
            sWt[c * C + half * 64 + oo] = sWpad[oo * HSTRIDE + c];
        }
        __syncthreads();
    }

    const float oe = 1.0f + epsp[0];

    for (int tile = blockIdx.x; tile < NTILES; tile += gridDim.x) {
        const int row0 = tile * TM;

        // ------------- Stage neighbor offsets (as float offsets into x) -------------
        for (int i = tid; i < TM * KNBR; i += THREADS) {
            int r = i >> 4;
            long long gi = (long long)(row0 + r) * KNBR + (i & 15);
            int s = is64 ? (int)w64[gi] : w32[gi];
            int bbase = ((row0 + r) >> 13) << 13;   // b * 8192
            sidx[i] = (bbase + s) << 7;             // (b*8192 + src) * 128
        }
        __syncthreads();

        // ------------- Gather + eps-residual: h tile -------------
        {
            const int r = tid >> 2;      // 0..63 : row within tile
            const int p = tid & 3;       // 0..3  : channel part (32 ch each)
            const float* xs = x + (size_t)(row0 + r) * C + 4 * p;

            float4 acc[8];
            #pragma unroll
            for (int j = 0; j < 8; j++) {
                float4 v = *(const float4*)(xs + 16 * j);
                acc[j].x = v.x * oe; acc[j].y = v.y * oe;
                acc[j].z = v.z * oe; acc[j].w = v.w * oe;
            }

            int offs[KNBR];
            #pragma unroll
            for (int k = 0; k < KNBR; k++) offs[k] = sidx[r * KNBR + k];

            #pragma unroll 4
            for (int k = 0; k < KNBR; k++) {
                const float* xn = x + offs[k] + 4 * p;
                #pragma unroll
                for (int j = 0; j < 8; j++) {
                    float4 v = *(const float4*)(xn + 16 * j);
                    acc[j].x += v.x; acc[j].y += v.y;
                    acc[j].z += v.z; acc[j].w += v.w;
                }
            }

            #pragma unroll
            for (int j = 0; j < 8; j++)
                *(float4*)(sh_h + r * HSTRIDE + 16 * j + 4 * p) = acc[j];
        }
        __syncthreads();

        // ------------- GEMM: out = relu(h @ W^T + b), 8 rows x 4 cols per thread -------------
        {
            const int ty = tid >> 5;     // 0..7 : rows ty*8 .. ty*8+7
            const int tx = tid & 31;     // cols 4*tx .. 4*tx+3

            float4 acc[8];
            #pragma unroll
            for (int i = 0; i < 8; i++) acc[i] = make_float4(0.f, 0.f, 0.f, 0.f);

            const float* hp = sh_h + ty * 8 * HSTRIDE;

            #pragma unroll 2
            for (int c = 0; c < C; c += 4) {
                float4 w0 = *(const float4*)(sWt + (c + 0) * C + 4 * tx);
                float4 w1 = *(const float4*)(sWt + (c + 1) * C + 4 * tx);
                float4 w2 = *(const float4*)(sWt + (c + 2) * C + 4 * tx);
                float4 w3 = *(const float4*)(sWt + (c + 3) * C + 4 * tx);
                #pragma unroll
                for (int i = 0; i < 8; i++) {
                    float4 h = *(const float4*)(hp + i * HSTRIDE + c);
                    acc[i].x = fmaf(h.x, w0.x, acc[i].x);
                    acc[i].y = fmaf(h.x, w0.y, acc[i].y);
                    acc[i].z = fmaf(h.x, w0.z, acc[i].z);
                    acc[i].w = fmaf(h.x, w0.w, acc[i].w);
                    acc[i].x = fmaf(h.y, w1.x, acc[i].x);
                    acc[i].y = fmaf(h.y, w1.y, acc[i].y);
                    acc[i].z = fmaf(h.y, w1.z, acc[i].z);
                    acc[i].w = fmaf(h.y, w1.w, acc[i].w);
                    acc[i].x = fmaf(h.z, w2.x, acc[i].x);
                    acc[i].y = fmaf(h.z, w2.y, acc[i].y);
                    acc[i].z = fmaf(h.z, w2.z, acc[i].z);
                    acc[i].w = fmaf(h.z, w2.w, acc[i].w);
                    acc[i].x = fmaf(h.w, w3.x, acc[i].x);
                    acc[i].y = fmaf(h.w, w3.y, acc[i].y);
                    acc[i].z = fmaf(h.w, w3.z, acc[i].z);
                    acc[i].w = fmaf(h.w, w3.w, acc[i].w);
                }
            }

            float4 b4 = *(const float4*)(bias + 4 * tx);
            #pragma unroll
            for (int i = 0; i < 8; i++) {
                float4 o;
                o.x = fmaxf(acc[i].x + b4.x, 0.f);
                o.y = fmaxf(acc[i].y + b4.y, 0.f);
                o.z = fmaxf(acc[i].z + b4.z, 0.f);
                o.w = fmaxf(acc[i].w + b4.w, 0.f);
                *(float4*)(out + (size_t)(row0 + ty * 8 + i) * C + 4 * tx) = o;
            }
        }
        __syncthreads();   // protect sh_h/sidx before next tile's writes
    }
}

extern "C" void kernel_launch(void* const* d_in, const int* in_sizes, int n_in,
                              void* d_out, int out_size)
{
    const float* x    = (const float*)d_in[0];
    const void*  ei   = d_in[1];
    const float* W    = (const float*)d_in[2];
    const float* bias = (const float*)d_in[3];
    const float* eps  = (const float*)d_in[4];
    float*       out  = (float*)d_out;

    cudaFuncSetAttribute(gin_fused_kernel,
                         cudaFuncAttributeMaxDynamicSharedMemorySize, SMEM_BYTES);

    // Persistent-ish grid: 2 blocks per SM on GB300 (152 SMs)
    gin_fused_kernel<<<304, THREADS, SMEM_BYTES>>>(x, ei, W, bias, eps, out);
}

// round 3
// speedup vs baseline: 1.1176x; 1.1176x over previous
#include <cuda_runtime.h>

// Problem constants (fixed by the reference)
#define BATCH    4
#define NPB      8192      // nodes per batch
#define KNBR     16        // neighbors
#define C        128       // channels in == channels out
#define ROWS     (BATCH * NPB)   // 32768 total rows

// Tiling
#define TM       64        // rows per tile
#define THREADS  256
#define HSTRIDE  132       // padded h-tile row stride (floats), 16B-aligned
#define NTILES   (ROWS / TM)     // 512

#define SMEM_FLOATS (C * C + TM * HSTRIDE)
#define SMEM_BYTES  (SMEM_FLOATS * 4 + TM * KNBR * 4)

typedef unsigned long long u64;

__device__ __forceinline__ u64 fma2(u64 a, u64 b, u64 c) {
    u64 d;
    asm("fma.rn.f32x2 %0, %1, %2, %3;" : "=l"(d) : "l"(a), "l"(b), "l"(c));
    return d;
}
__device__ __forceinline__ u64 rep2(float v) {
    u64 d;
    asm("mov.b64 %0, {%1, %1};" : "=l"(d) : "f"(v));
    return d;
}
__device__ __forceinline__ float2 unpack2(u64 v) {
    float2 r;
    asm("mov.b64 {%0, %1}, %2;" : "=f"(r.x), "=f"(r.y) : "l"(v));
    return r;
}

__global__ __launch_bounds__(THREADS, 2)
void gin_fused_kernel(const float* __restrict__ x,
                      const void* __restrict__ ei_raw,
                      const float* __restrict__ W,
                      const float* __restrict__ bias,
                      const float* __restrict__ epsp,
                      float* __restrict__ out)
{
    extern __shared__ float smem[];
    float* sWt   = smem;                       // 128x128 : W^T  [c][o]
    float* sbuf  = smem + C * C;
    float* sh_h  = sbuf;                       // TM x HSTRIDE
    int*   sidx  = (int*)(sbuf + TM * HSTRIDE);
    float* sWpad = sbuf;                       // alias: staging for W transpose

    const int tid = threadIdx.x;

    // ---------------- dtype sniff for edge_index (int32 vs int64) ----------------
    // int64 with values < 8192 -> every odd 32-bit word is 0; int32 -> random.
    const int* w32 = (const int*)ei_raw;
    int orv = 0;
    #pragma unroll
    for (int t = 0; t < 64; t++) orv |= w32[t * 8192 + 1];
    const bool is64 = (orv == 0);
    const long long* w64 = (const long long*)ei_raw;

    // ---------------- One-time: transpose W into sWt[c][o] ----------------
    #pragma unroll
    for (int half = 0; half < 2; half++) {
        for (int i = tid; i < 64 * 32; i += THREADS) {          // float4 units
            int o  = i >> 5;
            int c4 = i & 31;
            float4 v = *(const float4*)(W + (size_t)(half * 64 + o) * C + 4 * c4);
            *(float4*)(sWpad + o * HSTRIDE + 4 * c4) = v;
        }
        __syncthreads();
        for (int i = tid; i < 64 * C; i += THREADS) {
            int oo = i & 63;
            int c  = i >> 6;
            sWt[c * C + half * 64 + oo] = sWpad[oo * HSTRIDE + c];
        }
        __syncthreads();
    }

    const float oe = 1.0f + epsp[0];

    for (int tile = blockIdx.x; tile < NTILES; tile += gridDim.x) {
        const int row0 = tile * TM;

        // ------------- Stage neighbor offsets (as float offsets into x) -------------
        for (int i = tid; i < TM * KNBR; i += THREADS) {
            int r = i >> 4;
            long long gi = (long long)(row0 + r) * KNBR + (i & 15);
            int s = is64 ? (int)w64[gi] : w32[gi];
            int bbase = ((row0 + r) >> 13) << 13;   // b * 8192
            sidx[i] = (bbase + s) << 7;             // (b*8192 + src) * 128
        }
        __syncthreads();

        // ------------- Gather + eps-residual: h tile -------------
        // Mapping: 8 threads per row, each owning 16B within each 128B line
        // -> every warp LDG covers 4 full 128B lines (optimal wavefronts).
        {
            const int r = tid >> 3;      // 0..31 : handles rows r and r+32
            const int p = tid & 7;       // 0..7  : 16B slice within each line

            float4 acc[2][4];
            #pragma unroll
            for (int hh = 0; hh < 2; hh++) {
                const float* xs = x + (size_t)(row0 + r + 32 * hh) * C + 4 * p;
                #pragma unroll
                for (int j = 0; j < 4; j++) {
                    float4 v = *(const float4*)(xs + 32 * j);
                    acc[hh][j].x = v.x * oe; acc[hh][j].y = v.y * oe;
                    acc[hh][j].z = v.z * oe; acc[hh][j].w = v.w * oe;
                }
            }

            #pragma unroll 2
            for (int k = 0; k < KNBR; k++) {
                const int off0 = sidx[r * KNBR + k];
                const int off1 = sidx[(r + 32) * KNBR + k];
                const float* xn0 = x + off0 + 4 * p;
                const float* xn1 = x + off1 + 4 * p;
                #pragma unroll
                for (int j = 0; j < 4; j++) {
                    float4 v0 = *(const float4*)(xn0 + 32 * j);
                    float4 v1 = *(const float4*)(xn1 + 32 * j);
                    acc[0][j].x += v0.x; acc[0][j].y += v0.y;
                    acc[0][j].z += v0.z; acc[0][j].w += v0.w;
                    acc[1][j].x += v1.x; acc[1][j].y += v1.y;
                    acc[1][j].z += v1.z; acc[1][j].w += v1.w;
                }
            }

            #pragma unroll
            for (int hh = 0; hh < 2; hh++)
                #pragma unroll
                for (int j = 0; j < 4; j++)
                    *(float4*)(sh_h + (r + 32 * hh) * HSTRIDE + 32 * j + 4 * p) = acc[hh][j];
        }
        __syncthreads();

        // ------------- GEMM: out = relu(h @ W^T + b) -------------
        // 8 rows x 4 cols per thread; packed fp32x2 FMAs (exact fp32).
        {
            const int ty = tid >> 5;     // 0..7 : rows ty*8 .. ty*8+7
            const int tx = tid & 31;     // cols 4*tx .. 4*tx+3

            u64 acc[8][2];
            #pragma unroll
            for (int i = 0; i < 8; i++) { acc[i][0] = 0ull; acc[i][1] = 0ull; }

            const float* hp = sh_h + ty * 8 * HSTRIDE;

            #pragma unroll 2
            for (int c = 0; c < C; c += 4) {
                // w[c..c+3][4tx..4tx+3], each row read as two packed f32x2
                ulonglong2 w0 = *(const ulonglong2*)(sWt + (c + 0) * C + 4 * tx);
                ulonglong2 w1 = *(const ulonglong2*)(sWt + (c + 1) * C + 4 * tx);
                ulonglong2 w2 = *(const ulonglong2*)(sWt + (c + 2) * C + 4 * tx);
                ulonglong2 w3 = *(const ulonglong2*)(sWt + (c + 3) * C + 4 * tx);
                #pragma unroll
                for (int i = 0; i < 8; i++) {
                    float4 h = *(const float4*)(hp + i * HSTRIDE + c);
                    u64 hx = rep2(h.x), hy = rep2(h.y), hz = rep2(h.z), hw = rep2(h.w);
                    acc[i][0] = fma2(hx, w0.x, acc[i][0]);
                    acc[i][1] = fma2(hx, w0.y, acc[i][1]);
                    acc[i][0] = fma2(hy, w1.x, acc[i][0]);
                    acc[i][1] = fma2(hy, w1.y, acc[i][1]);
                    acc[i][0] = fma2(hz, w2.x, acc[i][0]);
                    acc[i][1] = fma2(hz, w2.y, acc[i][1]);
                    acc[i][0] = fma2(hw, w3.x, acc[i][0]);
                    acc[i][1] = fma2(hw, w3.y, acc[i][1]);
                }
            }

            float4 b4 = *(const float4*)(bias + 4 * tx);
            #pragma unroll
            for (int i = 0; i < 8; i++) {
                float2 a0 = unpack2(acc[i][0]);
                float2 a1 = unpack2(acc[i][1]);
                float4 o;
                o.x = fmaxf(a0.x + b4.x, 0.f);
                o.y = fmaxf(a0.y + b4.y, 0.f);
                o.z = fmaxf(a1.x + b4.z, 0.f);
                o.w = fmaxf(a1.y + b4.w, 0.f);
                *(float4*)(out + (size_t)(row0 + ty * 8 + i) * C + 4 * tx) = o;
            }
        }
        __syncthreads();   // protect sh_h/sidx before next tile's writes
    }
}

extern "C" void kernel_launch(void* const* d_in, const int* in_sizes, int n_in,
                              void* d_out, int out_size)
{
    const float* x    = (const float*)d_in[0];
    const void*  ei   = d_in[1];
    const float* W    = (const float*)d_in[2];
    const float* bias = (const float*)d_in[3];
    const float* eps  = (const float*)d_in[4];
    float*       out  = (float*)d_out;

    cudaFuncSetAttribute(gin_fused_kernel,
                         cudaFuncAttributeMaxDynamicSharedMemorySize, SMEM_BYTES);

    gin_fused_kernel<<<304, THREADS, SMEM_BYTES>>>(x, ei, W, bias, eps, out);
}

// round 4
// speedup vs baseline: 1.2755x; 1.1413x over previous
#include <cuda_runtime.h>

// Problem constants (fixed by the reference)
#define BATCH    4
#define NPB      8192
#define KNBR     16
#define C        128
#define ROWS     (BATCH * NPB)   // 32768

// Tiling / pipeline
#define TM       32              // rows per tile
#define THREADS  256             // 4 producer warps + 4 consumer warps
#define HSTRIDE  132             // padded h row stride (floats), 16B aligned
#define NTILES   (ROWS / TM)     // 1024
#define GRID     304             // 2 blocks/SM on 152 SMs

// smem: sWt (128*128) + 2 h-buffers (TM*HSTRIDE each)
#define SMEM_FLOATS (C * C + 2 * TM * HSTRIDE)
#define SMEM_BYTES  (SMEM_FLOATS * 4)

typedef unsigned long long u64;

__device__ __forceinline__ u64 fma2(u64 a, u64 b, u64 c) {
    u64 d;
    asm("fma.rn.f32x2 %0, %1, %2, %3;" : "=l"(d) : "l"(a), "l"(b), "l"(c));
    return d;
}
__device__ __forceinline__ u64 rep2(float v) {
    u64 d;
    asm("mov.b64 %0, {%1, %1};" : "=l"(d) : "f"(v));
    return d;
}
__device__ __forceinline__ float2 unpack2(u64 v) {
    float2 r;
    asm("mov.b64 {%0, %1}, %2;" : "=f"(r.x), "=f"(r.y) : "l"(v));
    return r;
}
// Named barriers: full[s] = 1+s, empty[s] = 3+s ; all 256 threads counted.
__device__ __forceinline__ void bar_sync(int id) {
    asm volatile("bar.sync %0, 256;" :: "r"(id) : "memory");
}
__device__ __forceinline__ void bar_arrive(int id) {
    asm volatile("bar.arrive %0, 256;" :: "r"(id) : "memory");
}

__global__ __launch_bounds__(THREADS, 2)
void gin_fused_kernel(const float* __restrict__ x,
                      const void* __restrict__ ei_raw,
                      const float* __restrict__ W,
                      const float* __restrict__ bias,
                      const float* __restrict__ epsp,
                      float* __restrict__ out)
{
    extern __shared__ float smem[];
    float* sWt  = smem;                         // 128x128 : W^T [c][o]
    float* hbuf = smem + C * C;                 // 2 x (TM x HSTRIDE)
    float* sWpad = hbuf;                        // alias: W-transpose staging (needs 64*HSTRIDE=8448 floats; have 2*32*132=8448)

    const int tid = threadIdx.x;

    // ---------- dtype sniff: int64 (odd words all 0) vs int32 ----------
    const int* w32 = (const int*)ei_raw;
    int orv = 0;
    #pragma unroll
    for (int t = 0; t < 64; t++) orv |= w32[t * 8192 + 1];
    const bool is64 = (orv == 0);
    const long long* w64 = (const long long*)ei_raw;

    // ---------- one-time: transpose W into sWt[c][o] ----------
    #pragma unroll
    for (int half = 0; half < 2; half++) {
        for (int i = tid; i < 64 * 32; i += THREADS) {
            int o  = i >> 5;
            int c4 = i & 31;
            float4 v = *(const float4*)(W + (size_t)(half * 64 + o) * C + 4 * c4);
            *(float4*)(sWpad + o * HSTRIDE + 4 * c4) = v;
        }
        __syncthreads();
        for (int i = tid; i < 64 * C; i += THREADS) {
            int oo = i & 63;
            int c  = i >> 6;
            sWt[c * C + half * 64 + oo] = sWpad[oo * HSTRIDE + c];
        }
        __syncthreads();
    }

    const float oe = 1.0f + epsp[0];
    const bool producer = (tid < 128);

    int iter = 0;
    for (int tile = blockIdx.x; tile < NTILES; tile += GRID, iter++) {
        const int s = iter & 1;
        const int row0 = tile * TM;
        float* sh = hbuf + s * TM * HSTRIDE;

        if (producer) {
            // 8 threads per row; each owns one 16B slice of every 128B line.
            const int rl = tid >> 3;        // 0..15 : rows rl and rl+16
            const int p  = tid & 7;

            // backpressure: buffer s must have been consumed
            if (iter >= 2) bar_sync(3 + s);

            #pragma unroll
            for (int hh = 0; hh < 2; hh++) {
                const int row = row0 + rl + 16 * hh;
                const int bbase = (row >> 13) << 13;        // b * 8192

                // load this row's 16 neighbor indices (redundant across the
                // 8 row-threads; same 64B line -> L1 broadcast)
                int idxs[KNBR];
                if (!is64) {
                    const int4* ip = (const int4*)(w32 + (size_t)row * KNBR);
                    #pragma unroll
                    for (int q = 0; q < 4; q++) {
                        int4 v = ip[q];
                        idxs[4*q+0] = v.x; idxs[4*q+1] = v.y;
                        idxs[4*q+2] = v.z; idxs[4*q+3] = v.w;
                    }
                } else {
                    #pragma unroll
                    for (int k = 0; k < KNBR; k++)
                        idxs[k] = (int)w64[(size_t)row * KNBR + k];
                }
                #pragma unroll
                for (int k = 0; k < KNBR; k++)
                    idxs[k] = (bbase + idxs[k]) << 7;       // float offset into x

                const float* xs = x + ((size_t)row << 7) + 4 * p;
                float4 acc[4];
                #pragma unroll
                for (int j = 0; j < 4; j++) {
                    float4 v = *(const float4*)(xs + 32 * j);
                    acc[j].x = v.x * oe; acc[j].y = v.y * oe;
                    acc[j].z = v.z * oe; acc[j].w = v.w * oe;
                }
                #pragma unroll 4
                for (int k = 0; k < KNBR; k++) {
                    const float* xn = x + idxs[k] + 4 * p;
                    #pragma unroll
                    for (int j = 0; j < 4; j++) {
                        float4 v = *(const float4*)(xn + 32 * j);
                        acc[j].x += v.x; acc[j].y += v.y;
                        acc[j].z += v.z; acc[j].w += v.w;
                    }
                }
                #pragma unroll
                for (int j = 0; j < 4; j++)
                    *(float4*)(sh + (rl + 16 * hh) * HSTRIDE + 32 * j + 4 * p) = acc[j];
            }
            bar_arrive(1 + s);   // buffer s full
        } else {
            // consumer: 8 rows x 4 cols per thread
            const int ct = tid - 128;
            const int ty = ct >> 5;          // 0..3 : rows ty*8 .. ty*8+7
            const int tx = ct & 31;          // cols 4*tx .. 4*tx+3

            bar_sync(1 + s);                 // wait buffer s full

            u64 acc[8][2];
            #pragma unroll
            for (int i = 0; i < 8; i++) { acc[i][0] = 0ull; acc[i][1] = 0ull; }

            const float* hp = sh + ty * 8 * HSTRIDE;

            #pragma unroll 2
            for (int c = 0; c < C; c += 4) {
                ulonglong2 w0 = *(const ulonglong2*)(sWt + (c + 0) * C + 4 * tx);
                ulonglong2 w1 = *(const ulonglong2*)(sWt + (c + 1) * C + 4 * tx);
                ulonglong2 w2 = *(const ulonglong2*)(sWt + (c + 2) * C + 4 * tx);
                ulonglong2 w3 = *(const ulonglong2*)(sWt + (c + 3) * C + 4 * tx);
                #pragma unroll
                for (int i = 0; i < 8; i++) {
                    float4 h = *(const float4*)(hp + i * HSTRIDE + c);
                    u64 hx = rep2(h.x), hy = rep2(h.y), hz = rep2(h.z), hw = rep2(h.w);
                    acc[i][0] = fma2(hx, w0.x, acc[i][0]);
                    acc[i][1] = fma2(hx, w0.y, acc[i][1]);
                    acc[i][0] = fma2(hy, w1.x, acc[i][0]);
                    acc[i][1] = fma2(hy, w1.y, acc[i][1]);
                    acc[i][0] = fma2(hz, w2.x, acc[i][0]);
                    acc[i][1] = fma2(hz, w2.y, acc[i][1]);
                    acc[i][0] = fma2(hw, w3.x, acc[i][0]);
                    acc[i][1] = fma2(hw, w3.y, acc[i][1]);
                }
            }
            bar_arrive(3 + s);               // buffer s consumed

            float4 b4 = *(const float4*)(bias + 4 * tx);
            #pragma unroll
            for (int i = 0; i < 8; i++) {
                float2 a0 = unpack2(acc[i][0]);
                float2 a1 = unpack2(acc[i][1]);
                float4 o;
                o.x = fmaxf(a0.x + b4.x, 0.f);
                o.y = fmaxf(a0.y + b4.y, 0.f);
                o.z = fmaxf(a1.x + b4.z, 0.f);
                o.w = fmaxf(a1.y + b4.w, 0.f);
                *(float4*)(out + (size_t)(row0 + ty * 8 + i) * C + 4 * tx) = o;
            }
        }
    }
}

extern "C" void kernel_launch(void* const* d_in, const int* in_sizes, int n_in,
                              void* d_out, int out_size)
{
    const float* x    = (const float*)d_in[0];
    const void*  ei   = d_in[1];
    const float* W    = (const float*)d_in[2];
    const float* bias = (const float*)d_in[3];
    const float* eps  = (const float*)d_in[4];
    float*       out  = (float*)d_out;

    cudaFuncSetAttribute(gin_fused_kernel,
                         cudaFuncAttributeMaxDynamicSharedMemorySize, SMEM_BYTES);

    gin_fused_kernel<<<GRID, THREADS, SMEM_BYTES>>>(x, ei, W, bias, eps, out);
}